// round 1
// baseline (speedup 1.0000x reference)
#include <cuda_runtime.h>
#include <cuda_bf16.h>
#include <cstdint>

#define DI __device__ __forceinline__

// Problem dims
constexpr int B_    = 4;
constexpr int N_    = 4096;
constexpr int D_    = 1024;
constexpr int C_    = 4;
constexpr int M_ALL = B_ * N_;      // 16384 rows total
constexpr int KC    = 3 * D_;       // 3072: split-cat K (hi|hi|lo vs hi|lo|hi)
constexpr float SCALE = 0.03125f;   // 1/sqrt(1024)

// ---------------- scratch (__device__ globals, no runtime alloc) ----------------
__device__ __nv_bfloat16 g_xcat[(size_t)M_ALL * KC];     // x split, A-side [h|h|l]
__device__ __nv_bfloat16 g_wcat[3][(size_t)D_ * KC];     // Wq,Wk,Wv transposed+split, B-side [h|l|h]
__device__ __nv_bfloat16 g_qcat[(size_t)M_ALL * KC];     // Q split, A-side
__device__ __nv_bfloat16 g_kcat[(size_t)M_ALL * KC];     // K split, B-side
__device__ float g_v[(size_t)M_ALL * D_];                // V fp32
__device__ float g_s[(size_t)M_ALL * N_];                // scores, [(b*4096+n)*4096 + m]
__device__ float g_rmax[M_ALL];
__device__ float g_rinv[M_ALL];
__device__ float g_wpart[8][B_ * N_];
__device__ float g_w[B_ * N_];                           // column means of attn
__device__ float g_ppart[8][B_ * D_];
__device__ float g_pooled[B_ * D_];

// ---------------- small helpers ----------------
DI void split2(float v, __nv_bfloat16& h, __nv_bfloat16& l) {
    h = __float2bfloat16(v);
    l = __float2bfloat16(v - __bfloat162float(h));
}

// fast exp on FMA pipe (no MUFU). x expected <= 0. rel err ~2e-6.
DI float fast_exp(float x) {
    x = fmaxf(x, -80.0f);
    const float L2E = 1.4426950408889634f;
    float t = fmaf(x, L2E, 12582912.0f);    // round-to-nearest-int trick
    float n = t - 12582912.0f;
    float r = fmaf(x, L2E, -n);             // r in [-0.5, 0.5]
    float p = 1.3333558146428443e-3f;
    p = fmaf(p, r, 9.6181291976956254e-3f);
    p = fmaf(p, r, 5.5504108664821580e-2f);
    p = fmaf(p, r, 2.4022650695910071e-1f);
    p = fmaf(p, r, 6.9314718055994531e-1f);
    p = fmaf(p, r, 1.0f);
    int e = (int)n;                          // e in [-116, 0]
    float sc = __int_as_float((e + 127) << 23);
    return p * sc;
}

DI float warpRedMax(float v) {
    #pragma unroll
    for (int o = 16; o > 0; o >>= 1) v = fmaxf(v, __shfl_xor_sync(0xffffffffu, v, o));
    return v;
}
DI float warpRedSum(float v) {
    #pragma unroll
    for (int o = 16; o > 0; o >>= 1) v += __shfl_xor_sync(0xffffffffu, v, o);
    return v;
}

// ---------------- prep: split inputs ----------------
__global__ void k_split_x(const float* __restrict__ x) {
    int i = blockIdx.x * blockDim.x + threadIdx.x;     // over M_ALL*D_/2
    int m  = i / (D_ / 2);
    int d2 = (i % (D_ / 2)) * 2;
    float v0 = x[(size_t)m * D_ + d2];
    float v1 = x[(size_t)m * D_ + d2 + 1];
    __nv_bfloat16 h0, l0, h1, l1;
    split2(v0, h0, l0); split2(v1, h1, l1);
    __nv_bfloat162 hh; hh.x = h0; hh.y = h1;
    __nv_bfloat162 ll; ll.x = l0; ll.y = l1;
    size_t base = (size_t)m * KC + d2;
    *reinterpret_cast<__nv_bfloat162*>(&g_xcat[base])            = hh;
    *reinterpret_cast<__nv_bfloat162*>(&g_xcat[base + D_])       = hh;
    *reinterpret_cast<__nv_bfloat162*>(&g_xcat[base + 2 * D_])   = ll;
}

// W is [D, D] row-major (k, n). Store transposed split: wcat[n*KC + k'] = [h|l|h]
__global__ void k_split_w(const float* __restrict__ W, int which) {
    int i = blockIdx.x * blockDim.x + threadIdx.x;     // D_*D_
    int n = i / D_;
    int k = i % D_;
    float v = W[(size_t)k * D_ + n];
    __nv_bfloat16 h, l; split2(v, h, l);
    __nv_bfloat16* dst = g_wcat[which];
    size_t base = (size_t)n * KC + k;
    dst[base]          = h;
    dst[base + D_]     = l;
    dst[base + 2 * D_] = h;
}

// ---------------- GEMM: C[M,N] = A[M,K'] * B[N,K']^T (both K-contiguous bf16) ----------------
constexpr int BM = 128, BN = 128, BK = 32;
constexpr int LDS_ = 40;                 // padded smem row (bf16 elems) -> conflict-free ldmatrix
constexpr int BUF_BYTES = BM * LDS_ * 2; // 10240 per buffer

DI unsigned sptr(const void* p) { return (unsigned)__cvta_generic_to_shared(p); }
DI void cp16(unsigned dst, const void* src) {
    asm volatile("cp.async.cg.shared.global [%0], [%1], 16;\n" :: "r"(dst), "l"(src));
}
DI void cp_commit() { asm volatile("cp.async.commit_group;\n"); }
template<int Nn> DI void cp_wait() { asm volatile("cp.async.wait_group %0;\n" :: "n"(Nn)); }
DI void ldsm4(unsigned a, uint32_t& r0, uint32_t& r1, uint32_t& r2, uint32_t& r3) {
    asm volatile("ldmatrix.sync.aligned.m8n8.x4.shared.b16 {%0,%1,%2,%3}, [%4];\n"
                 : "=r"(r0), "=r"(r1), "=r"(r2), "=r"(r3) : "r"(a));
}
DI void mma16816(float* c, const uint32_t* a, const uint32_t* b) {
    asm volatile("mma.sync.aligned.m16n8k16.row.col.f32.bf16.bf16.f32 "
                 "{%0,%1,%2,%3}, {%4,%5,%6,%7}, {%8,%9}, {%0,%1,%2,%3};\n"
                 : "+f"(c[0]), "+f"(c[1]), "+f"(c[2]), "+f"(c[3])
                 : "r"(a[0]), "r"(a[1]), "r"(a[2]), "r"(a[3]), "r"(b[0]), "r"(b[1]));
}

// JOB: 0 = Q proj (epilogue: bf16 split, A-side layout h|h|l)
//      1 = K proj (epilogue: bf16 split, B-side layout h|l|h)
//      2 = V proj (epilogue: fp32 + bias)
//      3 = scores (epilogue: fp32 * SCALE), z = batch
template<int JOB>
__global__ __launch_bounds__(256)
void k_gemm(const float* __restrict__ bias)
{
    __shared__ __nv_bfloat16 smA[2][BM * LDS_];
    __shared__ __nv_bfloat16 smB[2][BN * LDS_];

    const __nv_bfloat16* A;
    const __nv_bfloat16* Bm;
    if (JOB == 0)      { A = g_xcat; Bm = g_wcat[0]; }
    else if (JOB == 1) { A = g_xcat; Bm = g_wcat[1]; }
    else if (JOB == 2) { A = g_xcat; Bm = g_wcat[2]; }
    else               { A = g_qcat; Bm = g_kcat;   }

    const int K = KC;
    const int bm = blockIdx.y * BM;
    const int bn = blockIdx.x * BN;
    const int bz = blockIdx.z;
    if (JOB == 3) {
        A  += (size_t)bz * N_ * KC;
        Bm += (size_t)bz * N_ * KC;
    }
    A  += (size_t)bm * K;
    Bm += (size_t)bn * K;

    const int tid = threadIdx.x, lane = tid & 31, warp = tid >> 5;
    const int wm = warp >> 2;            // 0..1 (64 rows each)
    const int wn = warp & 3;             // 0..3 (32 cols each)

    // load mapping: each thread does 2 A chunks + 2 B chunks of 16B
    const int lrow = tid >> 2;           // 0..63
    const int lch  = (tid & 3) * 8;      // elem offset {0,8,16,24}
    const unsigned sA = sptr(smA), sB = sptr(smB);
    const unsigned ldst = (unsigned)((lrow * LDS_ + lch) * 2);
    const unsigned ldst2 = (unsigned)(((lrow + 64) * LDS_ + lch) * 2);

    auto load_tile = [&](int buf, int kt) {
        const __nv_bfloat16* a0 = A + (size_t)lrow * K + kt * BK + lch;
        const __nv_bfloat16* b0 = Bm + (size_t)lrow * K + kt * BK + lch;
        unsigned o = (unsigned)(buf * BUF_BYTES);
        cp16(sA + o + ldst,  a0);
        cp16(sA + o + ldst2, a0 + (size_t)64 * K);
        cp16(sB + o + ldst,  b0);
        cp16(sB + o + ldst2, b0 + (size_t)64 * K);
    };

    // ldmatrix per-lane offsets
    const int li = lane >> 3, lr = lane & 7;
    const unsigned aLane = (unsigned)((((li & 1) * 8 + lr) * LDS_ + (li >> 1) * 8) * 2);
    const unsigned bLane = (unsigned)((((li >> 1) * 8 + lr) * LDS_ + (li & 1) * 8) * 2);
    const unsigned wmB = (unsigned)(wm * 64 * LDS_ * 2);
    const unsigned wnB = (unsigned)(wn * 32 * LDS_ * 2);

    float acc[4][4][4];
    #pragma unroll
    for (int i = 0; i < 4; i++)
        #pragma unroll
        for (int j = 0; j < 4; j++)
            #pragma unroll
            for (int q = 0; q < 4; q++) acc[i][j][q] = 0.f;

    const int KT = K / BK;   // 96
    load_tile(0, 0); cp_commit();
    load_tile(1, 1); cp_commit();
    cp_wait<1>();
    __syncthreads();

    for (int kt = 0; kt < KT; ++kt) {
        const int buf = kt & 1;
        const unsigned oA = sA + buf * BUF_BYTES;
        const unsigned oB = sB + buf * BUF_BYTES;
        #pragma unroll
        for (int ks = 0; ks < 2; ++ks) {
            uint32_t a[4][4], b[4][2];
            #pragma unroll
            for (int mi = 0; mi < 4; ++mi)
                ldsm4(oA + wmB + (unsigned)(mi * 16 * LDS_ * 2) + (unsigned)(ks * 32) + aLane,
                      a[mi][0], a[mi][1], a[mi][2], a[mi][3]);
            #pragma unroll
            for (int nj = 0; nj < 2; ++nj)
                ldsm4(oB + wnB + (unsigned)(nj * 16 * LDS_ * 2) + (unsigned)(ks * 32) + bLane,
                      b[2 * nj][0], b[2 * nj][1], b[2 * nj + 1][0], b[2 * nj + 1][1]);
            #pragma unroll
            for (int mi = 0; mi < 4; ++mi)
                #pragma unroll
                for (int ni = 0; ni < 4; ++ni)
                    mma16816(acc[mi][ni], a[mi], b[ni]);
        }
        __syncthreads();
        if (kt + 2 < KT) load_tile(buf, kt + 2);
        cp_commit();
        cp_wait<1>();
        __syncthreads();
    }

    // epilogue
    const int row0 = bm + wm * 64 + (lane >> 2);
    const int col0 = bn + wn * 32 + (lane & 3) * 2;

    auto emit = [&](int r, int c, float v0, float v1) {
        if (JOB == 3) {
            float2 o; o.x = v0 * SCALE; o.y = v1 * SCALE;
            *reinterpret_cast<float2*>(&g_s[((size_t)bz * N_ + r) * N_ + c]) = o;
        } else if (JOB == 2) {
            float2 o; o.x = v0 + bias[c]; o.y = v1 + bias[c + 1];
            *reinterpret_cast<float2*>(&g_v[(size_t)r * D_ + c]) = o;
        } else {
            float w0 = v0 + bias[c], w1 = v1 + bias[c + 1];
            __nv_bfloat16 h0, l0, h1, l1;
            split2(w0, h0, l0); split2(w1, h1, l1);
            __nv_bfloat162 hh; hh.x = h0; hh.y = h1;
            __nv_bfloat162 ll; ll.x = l0; ll.y = l1;
            __nv_bfloat16* Cb = (JOB == 0) ? g_qcat : g_kcat;
            size_t base = (size_t)r * KC + c;
            if (JOB == 0) {   // A-side [h|h|l]
                *reinterpret_cast<__nv_bfloat162*>(&Cb[base])          = hh;
                *reinterpret_cast<__nv_bfloat162*>(&Cb[base + D_])     = hh;
                *reinterpret_cast<__nv_bfloat162*>(&Cb[base + 2 * D_]) = ll;
            } else {          // B-side [h|l|h]
                *reinterpret_cast<__nv_bfloat162*>(&Cb[base])          = hh;
                *reinterpret_cast<__nv_bfloat162*>(&Cb[base + D_])     = ll;
                *reinterpret_cast<__nv_bfloat162*>(&Cb[base + 2 * D_]) = hh;
            }
        }
    };

    #pragma unroll
    for (int mi = 0; mi < 4; ++mi) {
        #pragma unroll
        for (int ni = 0; ni < 4; ++ni) {
            int r = row0 + mi * 16;
            int c = col0 + ni * 8;
            emit(r,     c, acc[mi][ni][0], acc[mi][ni][1]);
            emit(r + 8, c, acc[mi][ni][2], acc[mi][ni][3]);
        }
    }
}

// ---------------- softmax pass A: per-row max & 1/sum ----------------
__global__ __launch_bounds__(256) void k_row() {
    const int row = blockIdx.x;                      // 0..16383
    const float4* S4 = reinterpret_cast<const float4*>(g_s + (size_t)row * N_);
    const int t = threadIdx.x, lane = t & 31, wid = t >> 5;
    float v[16];
    #pragma unroll
    for (int j = 0; j < 4; ++j) {
        float4 q = S4[t + 256 * j];
        v[4 * j] = q.x; v[4 * j + 1] = q.y; v[4 * j + 2] = q.z; v[4 * j + 3] = q.w;
    }
    float mx = v[0];
    #pragma unroll
    for (int i = 1; i < 16; ++i) mx = fmaxf(mx, v[i]);
    __shared__ float red[8];
    mx = warpRedMax(mx);
    if (lane == 0) red[wid] = mx;
    __syncthreads();
    float bm = red[0];
    #pragma unroll
    for (int i = 1; i < 8; ++i) bm = fmaxf(bm, red[i]);
    __syncthreads();
    float s = 0.f;
    #pragma unroll
    for (int i = 0; i < 16; ++i) s += fast_exp(v[i] - bm);
    s = warpRedSum(s);
    if (lane == 0) red[wid] = s;
    __syncthreads();
    if (t == 0) {
        float tot = 0.f;
        #pragma unroll
        for (int i = 0; i < 8; ++i) tot += red[i];
        g_rmax[row] = bm;
        g_rinv[row] = 1.0f / tot;
    }
}

// ---------------- softmax pass B: column means (deterministic chunked) ----------------
__global__ __launch_bounds__(256) void k_col() {
    // grid (16, B_, 8): x = column tile, y = batch, z = row chunk of 512
    const int b = blockIdx.y, z = blockIdx.z;
    const int col = blockIdx.x * 256 + threadIdx.x;
    const float* S  = g_s + (size_t)b * N_ * N_;
    const float* rm = g_rmax + b * N_;
    const float* ri = g_rinv + b * N_;
    const int n0 = z * 512;
    float a0 = 0.f, a1 = 0.f, a2 = 0.f, a3 = 0.f;
    for (int n = n0; n < n0 + 512; n += 4) {
        a0 += fast_exp(S[(size_t)(n    ) * N_ + col] - rm[n    ]) * ri[n    ];
        a1 += fast_exp(S[(size_t)(n + 1) * N_ + col] - rm[n + 1]) * ri[n + 1];
        a2 += fast_exp(S[(size_t)(n + 2) * N_ + col] - rm[n + 2]) * ri[n + 2];
        a3 += fast_exp(S[(size_t)(n + 3) * N_ + col] - rm[n + 3]) * ri[n + 3];
    }
    g_wpart[z][b * N_ + col] = (a0 + a1) + (a2 + a3);
}

__global__ void k_wreduce() {
    int i = blockIdx.x * blockDim.x + threadIdx.x;   // B_*N_
    float s = 0.f;
    #pragma unroll
    for (int z = 0; z < 8; ++z) s += g_wpart[z][i];
    g_w[i] = s * (1.0f / N_);
}

// ---------------- pooled = w @ V (deterministic chunked) ----------------
__global__ __launch_bounds__(256) void k_pool() {
    // grid (D_/256, B_, 8): z = m chunk of 512
    const int b = blockIdx.y, z = blockIdx.z;
    const int d = blockIdx.x * 256 + threadIdx.x;
    const float* V = g_v + (size_t)b * N_ * D_;
    const float* w = g_w + b * N_;
    const int m0 = z * 512;
    float a0 = 0.f, a1 = 0.f, a2 = 0.f, a3 = 0.f;
    for (int m = m0; m < m0 + 512; m += 4) {
        a0 += w[m    ] * V[(size_t)(m    ) * D_ + d];
        a1 += w[m + 1] * V[(size_t)(m + 1) * D_ + d];
        a2 += w[m + 2] * V[(size_t)(m + 2) * D_ + d];
        a3 += w[m + 3] * V[(size_t)(m + 3) * D_ + d];
    }
    g_ppart[z][b * D_ + d] = (a0 + a1) + (a2 + a3);
}

__global__ void k_preduce() {
    int i = blockIdx.x * blockDim.x + threadIdx.x;   // B_*D_
    float s = 0.f;
    #pragma unroll
    for (int z = 0; z < 8; ++z) s += g_ppart[z][i];
    g_pooled[i] = s;
}

// ---------------- classifier ----------------
__global__ void k_cls(const float* __restrict__ Wc, const float* __restrict__ bc,
                      float* __restrict__ out) {
    const int warp = threadIdx.x >> 5, lane = threadIdx.x & 31;
    const int b = warp >> 2, c = warp & 3;           // 16 warps
    float s = 0.f;
    for (int d = lane; d < D_; d += 32) s += g_pooled[b * D_ + d] * Wc[(size_t)d * C_ + c];
    s = warpRedSum(s);
    if (lane == 0) out[b * C_ + c] = fmaxf(s + bc[c], 0.0f);
}

// ---------------- launch ----------------
extern "C" void kernel_launch(void* const* d_in, const int* in_sizes, int n_in,
                              void* d_out, int out_size) {
    const float* x  = (const float*)d_in[0];
    const float* Wk = (const float*)d_in[1];
    const float* bk = (const float*)d_in[2];
    const float* Wq = (const float*)d_in[3];
    const float* bq = (const float*)d_in[4];
    const float* Wv = (const float*)d_in[5];
    const float* bv = (const float*)d_in[6];
    const float* Wc = (const float*)d_in[7];
    const float* bc = (const float*)d_in[8];
    float* out = (float*)d_out;

    // prep splits
    k_split_x<<<(M_ALL * D_ / 2) / 256, 256>>>(x);
    k_split_w<<<(D_ * D_) / 256, 256>>>(Wq, 0);
    k_split_w<<<(D_ * D_) / 256, 256>>>(Wk, 1);
    k_split_w<<<(D_ * D_) / 256, 256>>>(Wv, 2);

    // projections: M=16384, N=1024, K'=3072
    dim3 gProj(D_ / BN, M_ALL / BM, 1);
    k_gemm<0><<<gProj, 256>>>(bq);   // Q -> g_qcat (split, A-side)
    k_gemm<1><<<gProj, 256>>>(bk);   // K -> g_kcat (split, B-side)
    k_gemm<2><<<gProj, 256>>>(bv);   // V -> g_v (fp32)

    // scores per batch: 4096x4096, K'=3072
    dim3 gS(N_ / BN, N_ / BM, B_);
    k_gemm<3><<<gS, 256>>>(nullptr);

    // softmax row stats, column means
    k_row<<<M_ALL, 256>>>();
    dim3 gC(N_ / 256, B_, 8);
    k_col<<<gC, 256>>>();
    k_wreduce<<<(B_ * N_) / 256, 256>>>();

    // pooled = w @ V, then classifier
    dim3 gP(D_ / 256, B_, 8);
    k_pool<<<gP, 256>>>();
    k_preduce<<<(B_ * D_) / 256, 256>>>();
    k_cls<<<1, 512>>>(Wc, bc, out);
}

// round 3
// speedup vs baseline: 2.0713x; 2.0713x over previous
#include <cuda_runtime.h>
#include <cuda_bf16.h>
#include <cuda_fp16.h>
#include <cstdint>

#define DI __device__ __forceinline__

// Problem dims
constexpr int B_    = 4;
constexpr int N_    = 4096;
constexpr int D_    = 1024;
constexpr int C_    = 4;
constexpr int M_ALL = B_ * N_;      // 16384 rows total
constexpr int KC    = 3 * D_;       // 3072: split-cat K for V path only
constexpr float SCALE = 0.03125f;   // 1/sqrt(1024)

// ---------------- scratch (__device__ globals, no runtime alloc) ----------------
__device__ __nv_bfloat16 g_xcat[(size_t)M_ALL * KC];   // x split [h|h|l] (V path, A-side)
__device__ __nv_bfloat16 g_wvcat[(size_t)D_ * KC];     // Wv transposed+split [h|l|h] (B-side)
__device__ __half g_xh[(size_t)M_ALL * D_];            // x fp16
__device__ __half g_wq16[(size_t)D_ * D_];             // Wq fp16 row-major [d,j]
__device__ __half g_wk16[(size_t)D_ * D_];             // Wk fp16 row-major [e,j]
__device__ __half g_Gt[(size_t)D_ * D_];               // Gt[e,d] = G[d,e], G = Wq Wk^T
__device__ __half g_P[(size_t)M_ALL * D_];             // P = x G, fp16
__device__ __half g_s16[(size_t)M_ALL * N_];           // scores fp16, [(b*4096+n)*4096+m]
__device__ float g_v[(size_t)M_ALL * D_];              // V fp32
__device__ float g_t[D_];                              // Wk @ bq
__device__ float g_c[M_ALL];                           // SCALE * x @ t  (per-column bias term)
__device__ float g_rmax[M_ALL];
__device__ float g_rinv[M_ALL];
__device__ float g_wpart[8][B_ * N_];
__device__ float g_w[B_ * N_];                         // column means of attn
__device__ float g_ppart[8][B_ * D_];
__device__ float g_pooled[B_ * D_];

// ---------------- small helpers ----------------
DI void split2(float v, __nv_bfloat16& h, __nv_bfloat16& l) {
    h = __float2bfloat16(v);
    l = __float2bfloat16(v - __bfloat162float(h));
}

// fast exp on FMA pipe (no MUFU). rel err ~2e-6.
DI float fast_exp(float x) {
    x = fmaxf(x, -80.0f);
    const float L2E = 1.4426950408889634f;
    float t = fmaf(x, L2E, 12582912.0f);
    float n = t - 12582912.0f;
    float r = fmaf(x, L2E, -n);
    float p = 1.3333558146428443e-3f;
    p = fmaf(p, r, 9.6181291976956254e-3f);
    p = fmaf(p, r, 5.5504108664821580e-2f);
    p = fmaf(p, r, 2.4022650695910071e-1f);
    p = fmaf(p, r, 6.9314718055994531e-1f);
    p = fmaf(p, r, 1.0f);
    int e = (int)n;
    float sc = __int_as_float((e + 127) << 23);
    return p * sc;
}

DI float warpRedMax(float v) {
    #pragma unroll
    for (int o = 16; o > 0; o >>= 1) v = fmaxf(v, __shfl_xor_sync(0xffffffffu, v, o));
    return v;
}
DI float warpRedSum(float v) {
    #pragma unroll
    for (int o = 16; o > 0; o >>= 1) v += __shfl_xor_sync(0xffffffffu, v, o);
    return v;
}

// ---------------- prep kernels ----------------
// x -> fp16 copy + bf16 split-cat (for V path)
__global__ void k_prep_x(const float* __restrict__ x) {
    int i = blockIdx.x * blockDim.x + threadIdx.x;     // over M_ALL*D_/2
    int m  = i / (D_ / 2);
    int d2 = (i % (D_ / 2)) * 2;
    float v0 = x[(size_t)m * D_ + d2];
    float v1 = x[(size_t)m * D_ + d2 + 1];
    // fp16
    *reinterpret_cast<__half2*>(&g_xh[(size_t)m * D_ + d2]) = __floats2half2_rn(v0, v1);
    // bf16 split
    __nv_bfloat16 h0, l0, h1, l1;
    split2(v0, h0, l0); split2(v1, h1, l1);
    __nv_bfloat162 hh; hh.x = h0; hh.y = h1;
    __nv_bfloat162 ll; ll.x = l0; ll.y = l1;
    size_t base = (size_t)m * KC + d2;
    *reinterpret_cast<__nv_bfloat162*>(&g_xcat[base])          = hh;
    *reinterpret_cast<__nv_bfloat162*>(&g_xcat[base + D_])     = hh;
    *reinterpret_cast<__nv_bfloat162*>(&g_xcat[base + 2 * D_]) = ll;
}

// Wv [D,D] row-major (k,n) -> transposed split wvcat[n*KC + k'] = [h|l|h]
__global__ void k_split_wv(const float* __restrict__ W) {
    int i = blockIdx.x * blockDim.x + threadIdx.x;     // D_*D_
    int n = i / D_;
    int k = i % D_;
    float v = W[(size_t)k * D_ + n];
    __nv_bfloat16 h, l; split2(v, h, l);
    size_t base = (size_t)n * KC + k;
    g_wvcat[base]          = h;
    g_wvcat[base + D_]     = l;
    g_wvcat[base + 2 * D_] = h;
}

// Wq,Wk -> fp16 straight cast (row-major, K-contiguous along output dim j)
__global__ void k_w16(const float* __restrict__ Wq, const float* __restrict__ Wk) {
    int i = blockIdx.x * blockDim.x + threadIdx.x;     // D_*D_/2
    int i2 = i * 2;
    *reinterpret_cast<__half2*>(&g_wq16[i2]) = __floats2half2_rn(Wq[i2], Wq[i2 + 1]);
    *reinterpret_cast<__half2*>(&g_wk16[i2]) = __floats2half2_rn(Wk[i2], Wk[i2 + 1]);
}

// t[d] = sum_j Wk[d,j] * bq[j]   (one block per d)
__global__ void k_mv1(const float* __restrict__ Wk, const float* __restrict__ bq) {
    const int d = blockIdx.x;
    const int t = threadIdx.x, lane = t & 31, wid = t >> 5;
    float s = 0.f;
    for (int j = t; j < D_; j += 256) s += Wk[(size_t)d * D_ + j] * bq[j];
    s = warpRedSum(s);
    __shared__ float red[8];
    if (lane == 0) red[wid] = s;
    __syncthreads();
    if (t == 0) {
        float tot = 0.f;
        #pragma unroll
        for (int i = 0; i < 8; ++i) tot += red[i];
        g_t[d] = tot;
    }
}

// c[row] = SCALE * sum_d x[row,d] * t[d]   (one block per row)
__global__ void k_mv2(const float* __restrict__ x) {
    const int row = blockIdx.x;
    const int t = threadIdx.x, lane = t & 31, wid = t >> 5;
    float s = 0.f;
    for (int d = t; d < D_; d += 256) s += x[(size_t)row * D_ + d] * g_t[d];
    s = warpRedSum(s);
    __shared__ float red[8];
    if (lane == 0) red[wid] = s;
    __syncthreads();
    if (t == 0) {
        float tot = 0.f;
        #pragma unroll
        for (int i = 0; i < 8; ++i) tot += red[i];
        g_c[row] = SCALE * tot;
    }
}

// ---------------- GEMM: C[M,N] = A[M,K] * B[N,K]^T (K-contiguous, 2-byte types) ----------------
constexpr int BM = 128, BN = 128, BK = 32;
constexpr int LDS_ = 40;                 // padded smem row -> conflict-free ldmatrix
constexpr int BUF_BYTES = BM * LDS_ * 2;

DI unsigned sptr(const void* p) { return (unsigned)__cvta_generic_to_shared(p); }
DI void cp16(unsigned dst, const void* src) {
    asm volatile("cp.async.cg.shared.global [%0], [%1], 16;\n" :: "r"(dst), "l"(src));
}
DI void cp_commit() { asm volatile("cp.async.commit_group;\n"); }
template<int Nn> DI void cp_wait() { asm volatile("cp.async.wait_group %0;\n" :: "n"(Nn)); }
DI void ldsm4(unsigned a, uint32_t& r0, uint32_t& r1, uint32_t& r2, uint32_t& r3) {
    asm volatile("ldmatrix.sync.aligned.m8n8.x4.shared.b16 {%0,%1,%2,%3}, [%4];\n"
                 : "=r"(r0), "=r"(r1), "=r"(r2), "=r"(r3) : "r"(a));
}
template<bool FP16>
DI void mma16816(float* c, const uint32_t* a, const uint32_t* b) {
    if constexpr (FP16)
        asm volatile("mma.sync.aligned.m16n8k16.row.col.f32.f16.f16.f32 "
                     "{%0,%1,%2,%3}, {%4,%5,%6,%7}, {%8,%9}, {%0,%1,%2,%3};\n"
                     : "+f"(c[0]), "+f"(c[1]), "+f"(c[2]), "+f"(c[3])
                     : "r"(a[0]), "r"(a[1]), "r"(a[2]), "r"(a[3]), "r"(b[0]), "r"(b[1]));
    else
        asm volatile("mma.sync.aligned.m16n8k16.row.col.f32.bf16.bf16.f32 "
                     "{%0,%1,%2,%3}, {%4,%5,%6,%7}, {%8,%9}, {%0,%1,%2,%3};\n"
                     : "+f"(c[0]), "+f"(c[1]), "+f"(c[2]), "+f"(c[3])
                     : "r"(a[0]), "r"(a[1]), "r"(a[2]), "r"(a[3]), "r"(b[0]), "r"(b[1]));
}

// JOB: 0 = Gt   = Wk * Wq^T        (K=1024, fp16; Gt[e,d] = sum_j Wk[e,j]Wq[d,j] = G[d,e])
//      1 = P    = xh * Gt^T        (K=1024, fp16 in/out)
//      2 = V    = xcat * wvcat^T   (K=3072, bf16 in, fp32+bias out)
//      3 = scores = P * xh^T       (K=1024, fp16 in, fp16*SCALE + c_m out), z=batch
template<int JOB>
__global__ __launch_bounds__(256)
void k_gemm(const float* __restrict__ bias)
{
    constexpr bool FP16 = (JOB != 2);
    constexpr int  K    = (JOB == 2) ? KC : D_;

    __shared__ __nv_bfloat16 smA[2][BM * LDS_];
    __shared__ __nv_bfloat16 smB[2][BN * LDS_];

    const __nv_bfloat16* A;
    const __nv_bfloat16* Bm;
    const int bz = blockIdx.z;
    if (JOB == 0)      { A = (const __nv_bfloat16*)g_wk16; Bm = (const __nv_bfloat16*)g_wq16; }
    else if (JOB == 1) { A = (const __nv_bfloat16*)g_xh;   Bm = (const __nv_bfloat16*)g_Gt; }
    else if (JOB == 2) { A = g_xcat;                       Bm = g_wvcat; }
    else               { A = (const __nv_bfloat16*)g_P  + (size_t)bz * N_ * D_;
                         Bm = (const __nv_bfloat16*)g_xh + (size_t)bz * N_ * D_; }

    const int bm = blockIdx.y * BM;
    const int bn = blockIdx.x * BN;
    A  += (size_t)bm * K;
    Bm += (size_t)bn * K;

    const int tid = threadIdx.x, lane = tid & 31, warp = tid >> 5;
    const int wm = warp >> 2;
    const int wn = warp & 3;

    const int lrow = tid >> 2;
    const int lch  = (tid & 3) * 8;
    const unsigned sA = sptr(smA), sB = sptr(smB);
    const unsigned ldst  = (unsigned)((lrow * LDS_ + lch) * 2);
    const unsigned ldst2 = (unsigned)(((lrow + 64) * LDS_ + lch) * 2);

    auto load_tile = [&](int buf, int kt) {
        const __nv_bfloat16* a0 = A  + (size_t)lrow * K + kt * BK + lch;
        const __nv_bfloat16* b0 = Bm + (size_t)lrow * K + kt * BK + lch;
        unsigned o = (unsigned)(buf * BUF_BYTES);
        cp16(sA + o + ldst,  a0);
        cp16(sA + o + ldst2, a0 + (size_t)64 * K);
        cp16(sB + o + ldst,  b0);
        cp16(sB + o + ldst2, b0 + (size_t)64 * K);
    };

    const int li = lane >> 3, lr = lane & 7;
    const unsigned aLane = (unsigned)((((li & 1) * 8 + lr) * LDS_ + (li >> 1) * 8) * 2);
    const unsigned bLane = (unsigned)((((li >> 1) * 8 + lr) * LDS_ + (li & 1) * 8) * 2);
    const unsigned wmB = (unsigned)(wm * 64 * LDS_ * 2);
    const unsigned wnB = (unsigned)(wn * 32 * LDS_ * 2);

    float acc[4][4][4];
    #pragma unroll
    for (int i = 0; i < 4; i++)
        #pragma unroll
        for (int j = 0; j < 4; j++)
            #pragma unroll
            for (int q = 0; q < 4; q++) acc[i][j][q] = 0.f;

    const int KT = K / BK;
    load_tile(0, 0); cp_commit();
    load_tile(1, 1); cp_commit();
    cp_wait<1>();
    __syncthreads();

    for (int kt = 0; kt < KT; ++kt) {
        const int buf = kt & 1;
        const unsigned oA = sA + buf * BUF_BYTES;
        const unsigned oB = sB + buf * BUF_BYTES;
        #pragma unroll
        for (int ks = 0; ks < 2; ++ks) {
            uint32_t a[4][4], b[4][2];
            #pragma unroll
            for (int mi = 0; mi < 4; ++mi)
                ldsm4(oA + wmB + (unsigned)(mi * 16 * LDS_ * 2) + (unsigned)(ks * 32) + aLane,
                      a[mi][0], a[mi][1], a[mi][2], a[mi][3]);
            #pragma unroll
            for (int nj = 0; nj < 2; ++nj)
                ldsm4(oB + wnB + (unsigned)(nj * 16 * LDS_ * 2) + (unsigned)(ks * 32) + bLane,
                      b[2 * nj][0], b[2 * nj][1], b[2 * nj + 1][0], b[2 * nj + 1][1]);
            #pragma unroll
            for (int mi = 0; mi < 4; ++mi)
                #pragma unroll
                for (int ni = 0; ni < 4; ++ni)
                    mma16816<FP16>(acc[mi][ni], a[mi], b[ni]);
        }
        __syncthreads();
        if (kt + 2 < KT) load_tile(buf, kt + 2);
        cp_commit();
        cp_wait<1>();
        __syncthreads();
    }

    // epilogue
    const int row0 = bm + wm * 64 + (lane >> 2);
    const int col0 = bn + wn * 32 + (lane & 3) * 2;

    auto emit = [&](int r, int c, float v0, float v1) {
        if (JOB == 0) {
            *reinterpret_cast<__half2*>(&g_Gt[(size_t)r * D_ + c]) = __floats2half2_rn(v0, v1);
        } else if (JOB == 1) {
            *reinterpret_cast<__half2*>(&g_P[(size_t)r * D_ + c]) = __floats2half2_rn(v0, v1);
        } else if (JOB == 2) {
            float2 o; o.x = v0 + bias[c]; o.y = v1 + bias[c + 1];
            *reinterpret_cast<float2*>(&g_v[(size_t)r * D_ + c]) = o;
        } else {
            float s0 = fmaf(v0, SCALE, g_c[bz * N_ + c]);
            float s1 = fmaf(v1, SCALE, g_c[bz * N_ + c + 1]);
            *reinterpret_cast<__half2*>(&g_s16[((size_t)bz * N_ + r) * N_ + c]) =
                __floats2half2_rn(s0, s1);
        }
    };

    #pragma unroll
    for (int mi = 0; mi < 4; ++mi) {
        #pragma unroll
        for (int ni = 0; ni < 4; ++ni) {
            int r = row0 + mi * 16;
            int c = col0 + ni * 8;
            emit(r,     c, acc[mi][ni][0], acc[mi][ni][1]);
            emit(r + 8, c, acc[mi][ni][2], acc[mi][ni][3]);
        }
    }
}

// ---------------- softmax pass A: per-row max & 1/sum (fp16 scores) ----------------
__global__ __launch_bounds__(256) void k_row() {
    const int row = blockIdx.x;                      // 0..16383
    const __half2* S2 = reinterpret_cast<const __half2*>(g_s16 + (size_t)row * N_);
    const int t = threadIdx.x, lane = t & 31, wid = t >> 5;
    float v[16];
    #pragma unroll
    for (int j = 0; j < 8; ++j) {
        float2 f = __half22float2(S2[t + 256 * j]);
        v[2 * j] = f.x; v[2 * j + 1] = f.y;
    }
    float mx = v[0];
    #pragma unroll
    for (int i = 1; i < 16; ++i) mx = fmaxf(mx, v[i]);
    __shared__ float red[8];
    mx = warpRedMax(mx);
    if (lane == 0) red[wid] = mx;
    __syncthreads();
    float bm = red[0];
    #pragma unroll
    for (int i = 1; i < 8; ++i) bm = fmaxf(bm, red[i]);
    __syncthreads();
    float s = 0.f;
    #pragma unroll
    for (int i = 0; i < 16; ++i) s += fast_exp(v[i] - bm);
    s = warpRedSum(s);
    if (lane == 0) red[wid] = s;
    __syncthreads();
    if (t == 0) {
        float tot = 0.f;
        #pragma unroll
        for (int i = 0; i < 8; ++i) tot += red[i];
        g_rmax[row] = bm;
        g_rinv[row] = 1.0f / tot;
    }
}

// ---------------- softmax pass B: column partial means ----------------
__global__ __launch_bounds__(256) void k_col() {
    // grid (16, B_, 8)
    const int b = blockIdx.y, z = blockIdx.z;
    const int col = blockIdx.x * 256 + threadIdx.x;
    const __half* S = g_s16 + (size_t)b * N_ * N_;
    const float* rm = g_rmax + b * N_;
    const float* ri = g_rinv + b * N_;
    const int n0 = z * 512;
    float a0 = 0.f, a1 = 0.f, a2 = 0.f, a3 = 0.f;
    for (int n = n0; n < n0 + 512; n += 4) {
        a0 += fast_exp(__half2float(S[(size_t)(n    ) * N_ + col]) - rm[n    ]) * ri[n    ];
        a1 += fast_exp(__half2float(S[(size_t)(n + 1) * N_ + col]) - rm[n + 1]) * ri[n + 1];
        a2 += fast_exp(__half2float(S[(size_t)(n + 2) * N_ + col]) - rm[n + 2]) * ri[n + 2];
        a3 += fast_exp(__half2float(S[(size_t)(n + 3) * N_ + col]) - rm[n + 3]) * ri[n + 3];
    }
    g_wpart[z][b * N_ + col] = (a0 + a1) + (a2 + a3);
}

__global__ void k_wreduce() {
    int i = blockIdx.x * blockDim.x + threadIdx.x;   // B_*N_
    float s = 0.f;
    #pragma unroll
    for (int z = 0; z < 8; ++z) s += g_wpart[z][i];
    g_w[i] = s * (1.0f / N_);
}

// ---------------- pooled = w @ V ----------------
__global__ __launch_bounds__(256) void k_pool() {
    const int b = blockIdx.y, z = blockIdx.z;
    const int d = blockIdx.x * 256 + threadIdx.x;
    const float* V = g_v + (size_t)b * N_ * D_;
    const float* w = g_w + b * N_;
    const int m0 = z * 512;
    float a0 = 0.f, a1 = 0.f, a2 = 0.f, a3 = 0.f;
    for (int m = m0; m < m0 + 512; m += 4) {
        a0 += w[m    ] * V[(size_t)(m    ) * D_ + d];
        a1 += w[m + 1] * V[(size_t)(m + 1) * D_ + d];
        a2 += w[m + 2] * V[(size_t)(m + 2) * D_ + d];
        a3 += w[m + 3] * V[(size_t)(m + 3) * D_ + d];
    }
    g_ppart[z][b * D_ + d] = (a0 + a1) + (a2 + a3);
}

__global__ void k_preduce() {
    int i = blockIdx.x * blockDim.x + threadIdx.x;   // B_*D_
    float s = 0.f;
    #pragma unroll
    for (int z = 0; z < 8; ++z) s += g_ppart[z][i];
    g_pooled[i] = s;
}

// ---------------- classifier ----------------
__global__ void k_cls(const float* __restrict__ Wc, const float* __restrict__ bc,
                      float* __restrict__ out) {
    const int warp = threadIdx.x >> 5, lane = threadIdx.x & 31;
    const int b = warp >> 2, c = warp & 3;
    float s = 0.f;
    for (int d = lane; d < D_; d += 32) s += g_pooled[b * D_ + d] * Wc[(size_t)d * C_ + c];
    s = warpRedSum(s);
    if (lane == 0) out[b * C_ + c] = fmaxf(s + bc[c], 0.0f);
}

// ---------------- launch ----------------
extern "C" void kernel_launch(void* const* d_in, const int* in_sizes, int n_in,
                              void* d_out, int out_size) {
    const float* x  = (const float*)d_in[0];
    const float* Wk = (const float*)d_in[1];
    const float* bk = (const float*)d_in[2];
    const float* Wq = (const float*)d_in[3];
    const float* bq = (const float*)d_in[4];
    const float* Wv = (const float*)d_in[5];
    const float* bv = (const float*)d_in[6];
    const float* Wc = (const float*)d_in[7];
    const float* bc = (const float*)d_in[8];
    float* out = (float*)d_out;
    (void)bk;

    // prep
    k_prep_x<<<(M_ALL * D_ / 2) / 256, 256>>>(x);
    k_split_wv<<<(D_ * D_) / 256, 256>>>(Wv);
    k_w16<<<(D_ * D_ / 2) / 256, 256>>>(Wq, Wk);
    k_mv1<<<D_, 256>>>(Wk, bq);
    k_mv2<<<M_ALL, 256>>>(x);

    // Gt = Wk * Wq^T : [1024,1024], K=1024
    dim3 gG(D_ / BN, D_ / BM, 1);
    k_gemm<0><<<gG, 256>>>(nullptr);

    // P = xh * Gt^T : [16384,1024], K=1024
    dim3 gP1(D_ / BN, M_ALL / BM, 1);
    k_gemm<1><<<gP1, 256>>>(nullptr);

    // V = xcat * wvcat^T : [16384,1024], K=3072
    k_gemm<2><<<gP1, 256>>>(bv);

    // scores = P * xh^T per batch: [4096,4096], K=1024
    dim3 gS(N_ / BN, N_ / BM, B_);
    k_gemm<3><<<gS, 256>>>(nullptr);

    // softmax stats + column means
    k_row<<<M_ALL, 256>>>();
    dim3 gC(N_ / 256, B_, 8);
    k_col<<<gC, 256>>>();
    k_wreduce<<<(B_ * N_) / 256, 256>>>();

    // pooled = w @ V, classifier
    dim3 gP(D_ / 256, B_, 8);
    k_pool<<<gP, 256>>>();
    k_preduce<<<(B_ * D_) / 256, 256>>>();
    k_cls<<<1, 512>>>(Wc, bc, out);
}

// round 4
// speedup vs baseline: 2.5080x; 1.2108x over previous
#include <cuda_runtime.h>
#include <cuda_fp16.h>
#include <cstdint>

#define DI __device__ __forceinline__

// Problem dims
constexpr int B_    = 4;
constexpr int N_    = 4096;
constexpr int D_    = 1024;
constexpr int C_    = 4;
constexpr int M_ALL = B_ * N_;      // 16384 rows total
constexpr float SCALE = 0.03125f;   // 1/sqrt(1024)

// ---------------- scratch (__device__ globals, no runtime alloc) ----------------
__device__ __half g_xh[(size_t)M_ALL * D_];            // x fp16
__device__ __half g_wq16[(size_t)D_ * D_];             // Wq fp16 row-major [d,j]
__device__ __half g_wk16[(size_t)D_ * D_];             // Wk fp16 row-major [e,j]
__device__ __half g_Gt[(size_t)D_ * D_];               // Gt[e,d] = G[d,e], G = Wq Wk^T
__device__ __half g_P[(size_t)M_ALL * D_];             // P = x G, fp16
__device__ __half g_s16[(size_t)M_ALL * N_];           // scores fp16, [(b*4096+n)*4096+m]
__device__ float g_t[D_];                              // Wk @ bq
__device__ float g_c[M_ALL];                           // SCALE * x @ t  (per-column bias)
__device__ float g_rmax[M_ALL];
__device__ float g_rinv[M_ALL];
__device__ float g_wpart[8][B_ * N_];
__device__ float g_w[B_ * N_];                         // column means of attn
__device__ float g_ypart[8][B_ * D_];
__device__ float g_y[B_ * D_];                         // y_b = sum_m w_bm x_bm
__device__ float g_pooled[B_ * D_];

// ---------------- small helpers ----------------
// fast exp on FMA pipe (no MUFU). rel err ~2e-6.
DI float fast_exp(float x) {
    x = fmaxf(x, -80.0f);
    const float L2E = 1.4426950408889634f;
    float t = fmaf(x, L2E, 12582912.0f);
    float n = t - 12582912.0f;
    float r = fmaf(x, L2E, -n);
    float p = 1.3333558146428443e-3f;
    p = fmaf(p, r, 9.6181291976956254e-3f);
    p = fmaf(p, r, 5.5504108664821580e-2f);
    p = fmaf(p, r, 2.4022650695910071e-1f);
    p = fmaf(p, r, 6.9314718055994531e-1f);
    p = fmaf(p, r, 1.0f);
    int e = (int)n;
    float sc = __int_as_float((e + 127) << 23);
    return p * sc;
}

DI float warpRedMax(float v) {
    #pragma unroll
    for (int o = 16; o > 0; o >>= 1) v = fmaxf(v, __shfl_xor_sync(0xffffffffu, v, o));
    return v;
}
DI float warpRedSum(float v) {
    #pragma unroll
    for (int o = 16; o > 0; o >>= 1) v += __shfl_xor_sync(0xffffffffu, v, o);
    return v;
}

// ---------------- prep kernels ----------------
// x -> fp16
__global__ void k_x16(const float* __restrict__ x) {
    int i = blockIdx.x * blockDim.x + threadIdx.x;     // M_ALL*D_/4
    float4 v = reinterpret_cast<const float4*>(x)[i];
    __half2 a = __floats2half2_rn(v.x, v.y);
    __half2 b = __floats2half2_rn(v.z, v.w);
    uint2 o; o.x = *reinterpret_cast<uint32_t*>(&a); o.y = *reinterpret_cast<uint32_t*>(&b);
    reinterpret_cast<uint2*>(g_xh)[i] = o;
}

// Wq,Wk -> fp16 straight cast (row-major, K-contiguous along output dim j)
__global__ void k_w16(const float* __restrict__ Wq, const float* __restrict__ Wk) {
    int i = blockIdx.x * blockDim.x + threadIdx.x;     // D_*D_/2
    int i2 = i * 2;
    *reinterpret_cast<__half2*>(&g_wq16[i2]) = __floats2half2_rn(Wq[i2], Wq[i2 + 1]);
    *reinterpret_cast<__half2*>(&g_wk16[i2]) = __floats2half2_rn(Wk[i2], Wk[i2 + 1]);
}

// t[d] = sum_j Wk[d,j] * bq[j]   (one block per d)
__global__ void k_mv1(const float* __restrict__ Wk, const float* __restrict__ bq) {
    const int d = blockIdx.x;
    const int t = threadIdx.x, lane = t & 31, wid = t >> 5;
    float s = 0.f;
    for (int j = t; j < D_; j += 256) s += Wk[(size_t)d * D_ + j] * bq[j];
    s = warpRedSum(s);
    __shared__ float red[8];
    if (lane == 0) red[wid] = s;
    __syncthreads();
    if (t == 0) {
        float tot = 0.f;
        #pragma unroll
        for (int i = 0; i < 8; ++i) tot += red[i];
        g_t[d] = tot;
    }
}

// c[row] = SCALE * sum_d x[row,d] * t[d]   (one block per row)
__global__ void k_mv2(const float* __restrict__ x) {
    const int row = blockIdx.x;
    const int t = threadIdx.x, lane = t & 31, wid = t >> 5;
    float s = 0.f;
    for (int d = t; d < D_; d += 256) s += x[(size_t)row * D_ + d] * g_t[d];
    s = warpRedSum(s);
    __shared__ float red[8];
    if (lane == 0) red[wid] = s;
    __syncthreads();
    if (t == 0) {
        float tot = 0.f;
        #pragma unroll
        for (int i = 0; i < 8; ++i) tot += red[i];
        g_c[row] = SCALE * tot;
    }
}

// ---------------- GEMM: C[M,N] = A[M,K] * B[N,K]^T (K-contiguous fp16) ----------------
constexpr int BM = 128, BN = 128, BK = 32;
constexpr int LDS_ = 40;                 // padded smem row -> conflict-free ldmatrix
constexpr int BUF_BYTES = BM * LDS_ * 2;

DI unsigned sptr(const void* p) { return (unsigned)__cvta_generic_to_shared(p); }
DI void cp16(unsigned dst, const void* src) {
    asm volatile("cp.async.cg.shared.global [%0], [%1], 16;\n" :: "r"(dst), "l"(src));
}
DI void cp_commit() { asm volatile("cp.async.commit_group;\n"); }
template<int Nn> DI void cp_wait() { asm volatile("cp.async.wait_group %0;\n" :: "n"(Nn)); }
DI void ldsm4(unsigned a, uint32_t& r0, uint32_t& r1, uint32_t& r2, uint32_t& r3) {
    asm volatile("ldmatrix.sync.aligned.m8n8.x4.shared.b16 {%0,%1,%2,%3}, [%4];\n"
                 : "=r"(r0), "=r"(r1), "=r"(r2), "=r"(r3) : "r"(a));
}
DI void mma16816(float* c, const uint32_t* a, const uint32_t* b) {
    asm volatile("mma.sync.aligned.m16n8k16.row.col.f32.f16.f16.f32 "
                 "{%0,%1,%2,%3}, {%4,%5,%6,%7}, {%8,%9}, {%0,%1,%2,%3};\n"
                 : "+f"(c[0]), "+f"(c[1]), "+f"(c[2]), "+f"(c[3])
                 : "r"(a[0]), "r"(a[1]), "r"(a[2]), "r"(a[3]), "r"(b[0]), "r"(b[1]));
}

// JOB: 0 = Gt     = Wk * Wq^T   (Gt[e,d] = sum_j Wk[e,j]Wq[d,j] = G[d,e])
//      1 = P      = xh * Gt^T
//      3 = scores = P * xh^T    (fp16*SCALE + c_m out), z = batch
template<int JOB>
__global__ __launch_bounds__(256)
void k_gemm()
{
    constexpr int K = D_;

    __shared__ __half smA[2][BM * LDS_];
    __shared__ __half smB[2][BN * LDS_];

    const __half* A;
    const __half* Bm;
    const int bz = blockIdx.z;
    if (JOB == 0)      { A = g_wk16; Bm = g_wq16; }
    else if (JOB == 1) { A = g_xh;   Bm = g_Gt; }
    else               { A = g_P  + (size_t)bz * N_ * D_;
                         Bm = g_xh + (size_t)bz * N_ * D_; }

    const int bm = blockIdx.y * BM;
    const int bn = blockIdx.x * BN;
    A  += (size_t)bm * K;
    Bm += (size_t)bn * K;

    const int tid = threadIdx.x, lane = tid & 31, warp = tid >> 5;
    const int wm = warp >> 2;
    const int wn = warp & 3;

    const int lrow = tid >> 2;
    const int lch  = (tid & 3) * 8;
    const unsigned sA = sptr(smA), sB = sptr(smB);
    const unsigned ldst  = (unsigned)((lrow * LDS_ + lch) * 2);
    const unsigned ldst2 = (unsigned)(((lrow + 64) * LDS_ + lch) * 2);

    auto load_tile = [&](int buf, int kt) {
        const __half* a0 = A  + (size_t)lrow * K + kt * BK + lch;
        const __half* b0 = Bm + (size_t)lrow * K + kt * BK + lch;
        unsigned o = (unsigned)(buf * BUF_BYTES);
        cp16(sA + o + ldst,  a0);
        cp16(sA + o + ldst2, a0 + (size_t)64 * K);
        cp16(sB + o + ldst,  b0);
        cp16(sB + o + ldst2, b0 + (size_t)64 * K);
    };

    const int li = lane >> 3, lr = lane & 7;
    const unsigned aLane = (unsigned)((((li & 1) * 8 + lr) * LDS_ + (li >> 1) * 8) * 2);
    const unsigned bLane = (unsigned)((((li >> 1) * 8 + lr) * LDS_ + (li & 1) * 8) * 2);
    const unsigned wmB = (unsigned)(wm * 64 * LDS_ * 2);
    const unsigned wnB = (unsigned)(wn * 32 * LDS_ * 2);

    float acc[4][4][4];
    #pragma unroll
    for (int i = 0; i < 4; i++)
        #pragma unroll
        for (int j = 0; j < 4; j++)
            #pragma unroll
            for (int q = 0; q < 4; q++) acc[i][j][q] = 0.f;

    const int KT = K / BK;   // 32
    load_tile(0, 0); cp_commit();
    load_tile(1, 1); cp_commit();
    cp_wait<1>();
    __syncthreads();

    for (int kt = 0; kt < KT; ++kt) {
        const int buf = kt & 1;
        const unsigned oA = sA + buf * BUF_BYTES;
        const unsigned oB = sB + buf * BUF_BYTES;
        #pragma unroll
        for (int ks = 0; ks < 2; ++ks) {
            uint32_t a[4][4], b[4][2];
            #pragma unroll
            for (int mi = 0; mi < 4; ++mi)
                ldsm4(oA + wmB + (unsigned)(mi * 16 * LDS_ * 2) + (unsigned)(ks * 32) + aLane,
                      a[mi][0], a[mi][1], a[mi][2], a[mi][3]);
            #pragma unroll
            for (int nj = 0; nj < 2; ++nj)
                ldsm4(oB + wnB + (unsigned)(nj * 16 * LDS_ * 2) + (unsigned)(ks * 32) + bLane,
                      b[2 * nj][0], b[2 * nj][1], b[2 * nj + 1][0], b[2 * nj + 1][1]);
            #pragma unroll
            for (int mi = 0; mi < 4; ++mi)
                #pragma unroll
                for (int ni = 0; ni < 4; ++ni)
                    mma16816(acc[mi][ni], a[mi], b[ni]);
        }
        __syncthreads();
        if (kt + 2 < KT) load_tile(buf, kt + 2);
        cp_commit();
        cp_wait<1>();
        __syncthreads();
    }

    // epilogue
    const int row0 = bm + wm * 64 + (lane >> 2);
    const int col0 = bn + wn * 32 + (lane & 3) * 2;

    auto emit = [&](int r, int c, float v0, float v1) {
        if (JOB == 0) {
            *reinterpret_cast<__half2*>(&g_Gt[(size_t)r * D_ + c]) = __floats2half2_rn(v0, v1);
        } else if (JOB == 1) {
            *reinterpret_cast<__half2*>(&g_P[(size_t)r * D_ + c]) = __floats2half2_rn(v0, v1);
        } else {
            float s0 = fmaf(v0, SCALE, g_c[bz * N_ + c]);
            float s1 = fmaf(v1, SCALE, g_c[bz * N_ + c + 1]);
            *reinterpret_cast<__half2*>(&g_s16[((size_t)bz * N_ + r) * N_ + c]) =
                __floats2half2_rn(s0, s1);
        }
    };

    #pragma unroll
    for (int mi = 0; mi < 4; ++mi) {
        #pragma unroll
        for (int ni = 0; ni < 4; ++ni) {
            int r = row0 + mi * 16;
            int c = col0 + ni * 8;
            emit(r,     c, acc[mi][ni][0], acc[mi][ni][1]);
            emit(r + 8, c, acc[mi][ni][2], acc[mi][ni][3]);
        }
    }
}

// ---------------- softmax pass A: per-row max & 1/sum (fp16 scores) ----------------
__global__ __launch_bounds__(256) void k_row() {
    const int row = blockIdx.x;                      // 0..16383
    const __half2* S2 = reinterpret_cast<const __half2*>(g_s16 + (size_t)row * N_);
    const int t = threadIdx.x, lane = t & 31, wid = t >> 5;
    float v[16];
    #pragma unroll
    for (int j = 0; j < 8; ++j) {
        float2 f = __half22float2(S2[t + 256 * j]);
        v[2 * j] = f.x; v[2 * j + 1] = f.y;
    }
    float mx = v[0];
    #pragma unroll
    for (int i = 1; i < 16; ++i) mx = fmaxf(mx, v[i]);
    __shared__ float red[8];
    mx = warpRedMax(mx);
    if (lane == 0) red[wid] = mx;
    __syncthreads();
    float bm = red[0];
    #pragma unroll
    for (int i = 1; i < 8; ++i) bm = fmaxf(bm, red[i]);
    __syncthreads();
    float s = 0.f;
    #pragma unroll
    for (int i = 0; i < 16; ++i) s += fast_exp(v[i] - bm);
    s = warpRedSum(s);
    if (lane == 0) red[wid] = s;
    __syncthreads();
    if (t == 0) {
        float tot = 0.f;
        #pragma unroll
        for (int i = 0; i < 8; ++i) tot += red[i];
        g_rmax[row] = bm;
        g_rinv[row] = 1.0f / tot;
    }
}

// ---------------- softmax pass B: column partial means ----------------
__global__ __launch_bounds__(256) void k_col() {
    // grid (16, B_, 8)
    const int b = blockIdx.y, z = blockIdx.z;
    const int col = blockIdx.x * 256 + threadIdx.x;
    const __half* S = g_s16 + (size_t)b * N_ * N_;
    const float* rm = g_rmax + b * N_;
    const float* ri = g_rinv + b * N_;
    const int n0 = z * 512;
    float a0 = 0.f, a1 = 0.f, a2 = 0.f, a3 = 0.f;
    for (int n = n0; n < n0 + 512; n += 4) {
        a0 += fast_exp(__half2float(S[(size_t)(n    ) * N_ + col]) - rm[n    ]) * ri[n    ];
        a1 += fast_exp(__half2float(S[(size_t)(n + 1) * N_ + col]) - rm[n + 1]) * ri[n + 1];
        a2 += fast_exp(__half2float(S[(size_t)(n + 2) * N_ + col]) - rm[n + 2]) * ri[n + 2];
        a3 += fast_exp(__half2float(S[(size_t)(n + 3) * N_ + col]) - rm[n + 3]) * ri[n + 3];
    }
    g_wpart[z][b * N_ + col] = (a0 + a1) + (a2 + a3);
}

__global__ void k_wreduce() {
    int i = blockIdx.x * blockDim.x + threadIdx.x;   // B_*N_
    float s = 0.f;
    #pragma unroll
    for (int z = 0; z < 8; ++z) s += g_wpart[z][i];
    g_w[i] = s * (1.0f / N_);
}

// ---------------- y_b = sum_m w_bm * x_bm (weighted row-sum of x, fp32) ----------------
__global__ __launch_bounds__(256) void k_wsum(const float* __restrict__ x) {
    // grid (D_/256, B_, 8): z = m chunk of 512
    const int b = blockIdx.y, z = blockIdx.z;
    const int d = blockIdx.x * 256 + threadIdx.x;
    const float* X = x + (size_t)b * N_ * D_;
    const float* w = g_w + b * N_;
    const int m0 = z * 512;
    float a0 = 0.f, a1 = 0.f, a2 = 0.f, a3 = 0.f;
    for (int m = m0; m < m0 + 512; m += 4) {
        a0 += w[m    ] * X[(size_t)(m    ) * D_ + d];
        a1 += w[m + 1] * X[(size_t)(m + 1) * D_ + d];
        a2 += w[m + 2] * X[(size_t)(m + 2) * D_ + d];
        a3 += w[m + 3] * X[(size_t)(m + 3) * D_ + d];
    }
    g_ypart[z][b * D_ + d] = (a0 + a1) + (a2 + a3);
}

__global__ void k_yreduce() {
    int i = blockIdx.x * blockDim.x + threadIdx.x;   // B_*D_
    float s = 0.f;
    #pragma unroll
    for (int z = 0; z < 8; ++z) s += g_ypart[z][i];
    g_y[i] = s;
}

// ---------------- pooled_b = y_b @ Wv + bv (fp32 matvec, coalesced over d) ----------------
__global__ __launch_bounds__(256) void k_vmv(const float* __restrict__ Wv,
                                             const float* __restrict__ bv) {
    // grid (D_/256, B_)
    const int b = blockIdx.y;
    const int d = blockIdx.x * 256 + threadIdx.x;
    const float* y = g_y + b * D_;
    float s = 0.f;
    #pragma unroll 4
    for (int k = 0; k < D_; ++k) s += y[k] * Wv[(size_t)k * D_ + d];
    g_pooled[b * D_ + d] = s + bv[d];
}

// ---------------- classifier ----------------
__global__ void k_cls(const float* __restrict__ Wc, const float* __restrict__ bc,
                      float* __restrict__ out) {
    const int warp = threadIdx.x >> 5, lane = threadIdx.x & 31;
    const int b = warp >> 2, c = warp & 3;
    float s = 0.f;
    for (int d = lane; d < D_; d += 32) s += g_pooled[b * D_ + d] * Wc[(size_t)d * C_ + c];
    s = warpRedSum(s);
    if (lane == 0) out[b * C_ + c] = fmaxf(s + bc[c], 0.0f);
}

// ---------------- launch ----------------
extern "C" void kernel_launch(void* const* d_in, const int* in_sizes, int n_in,
                              void* d_out, int out_size) {
    const float* x  = (const float*)d_in[0];
    const float* Wk = (const float*)d_in[1];
    const float* bk = (const float*)d_in[2];
    const float* Wq = (const float*)d_in[3];
    const float* bq = (const float*)d_in[4];
    const float* Wv = (const float*)d_in[5];
    const float* bv = (const float*)d_in[6];
    const float* Wc = (const float*)d_in[7];
    const float* bc = (const float*)d_in[8];
    float* out = (float*)d_out;
    (void)bk;

    // prep
    k_x16<<<(M_ALL * D_ / 4) / 256, 256>>>(x);
    k_w16<<<(D_ * D_ / 2) / 256, 256>>>(Wq, Wk);
    k_mv1<<<D_, 256>>>(Wk, bq);
    k_mv2<<<M_ALL, 256>>>(x);

    // Gt = Wk * Wq^T : [1024,1024], K=1024
    dim3 gG(D_ / BN, D_ / BM, 1);
    k_gemm<0><<<gG, 256>>>();

    // P = xh * Gt^T : [16384,1024], K=1024
    dim3 gP1(D_ / BN, M_ALL / BM, 1);
    k_gemm<1><<<gP1, 256>>>();

    // scores = P * xh^T per batch: [4096,4096], K=1024
    dim3 gS(N_ / BN, N_ / BM, B_);
    k_gemm<3><<<gS, 256>>>();

    // softmax stats + column means
    k_row<<<M_ALL, 256>>>();
    dim3 gC(N_ / 256, B_, 8);
    k_col<<<gC, 256>>>();
    k_wreduce<<<(B_ * N_) / 256, 256>>>();

    // y = w @ x, pooled = y @ Wv + bv, classifier
    dim3 gY(D_ / 256, B_, 8);
    k_wsum<<<gY, 256>>>(x);
    k_yreduce<<<(B_ * D_) / 256, 256>>>();
    dim3 gV(D_ / 256, B_);
    k_vmv<<<gV, 256>>>(Wv, bv);
    k_cls<<<1, 512>>>(Wc, bc, out);
}